// round 14
// baseline (speedup 1.0000x reference)
#include <cuda_runtime.h>
#include <cstdint>

#define Uv 2048
#define Bv 16
#define Tv 2048
#define Fv 128
#define NCTA 128
#define CPC 16
#define TK 512
#define THR 512
#define SMEM_MAIN (Uv*CPC*4 + 3*TK*Bv*4)   // 128KB W + 96KB h ring = 224KB

typedef unsigned long long u64;

__device__ __align__(16) float g_u[(size_t)Tv * Uv * Bv];   // [t][u][b]
__device__ __align__(16) float g_h[2][Uv * Bv];             // [buf][u][b]
__device__ unsigned g_c[4];                                 // per-region step counters
__device__ int   g_ci[Uv * 16];
__device__ float g_cv[Uv * 16];
__device__ int   g_cn[Uv];

__device__ __forceinline__ void fma2(u64& d, u64 a, u64 b) {
    asm("fma.rn.f32x2 %0, %1, %2, %0;" : "+l"(d) : "l"(a), "l"(b));
}
__device__ __forceinline__ void add2(u64& d, u64 a) {
    asm("add.rn.f32x2 %0, %1, %0;" : "+l"(d) : "l"(a));
}
__device__ __forceinline__ u64 dup32(float x) {
    u64 d; unsigned xi = __float_as_uint(x);
    asm("mov.b64 %0, {%1, %1};" : "=l"(d) : "r"(xi)); return d;
}
__device__ __forceinline__ unsigned sptr(const void* p) {
    unsigned r;
    asm("{ .reg .u64 t; cvta.to.shared.u64 t, %1; cvt.u32.u64 %0, t; }" : "=r"(r) : "l"(p));
    return r;
}
__device__ __forceinline__ void cpa16(unsigned dst, const float* src) {
    asm volatile("cp.async.cg.shared.global [%0], [%1], 16;" :: "r"(dst), "l"(src));
}
__device__ __forceinline__ unsigned ldacq(unsigned* p) {
    unsigned v;
    asm volatile("ld.acquire.gpu.u32 %0, [%1];" : "=r"(v) : "l"(p) : "memory");
    return v;
}
__device__ __forceinline__ void spinflag(unsigned* p, unsigned tgt) {
    while (ldacq(p) < tgt) {}
}
__device__ __forceinline__ u64 shfl_xor64(u64 v, int d) {
    unsigned lo = (unsigned)v, hi = (unsigned)(v >> 32);
    lo = __shfl_xor_sync(0xFFFFFFFFu, lo, d);
    hi = __shfl_xor_sync(0xFFFFFFFFu, hi, d);
    return (u64)lo | ((u64)hi << 32);
}

__global__ void k0() {
    int i = blockIdx.x * blockDim.x + threadIdx.x;
    if (i < 4) g_c[i] = 0u;
    if (i < Uv * Bv) g_h[0][i] = 0.0f;
}

__global__ void k_csc(const float* __restrict__ kern) {
    int u = blockIdx.x * blockDim.x + threadIdx.x;
    if (u >= Uv) return;
    int c = 0;
    for (int f = 0; f < Fv; f++) {
        float v = kern[(size_t)f * Uv + u];
        if (v != 0.0f) { g_ci[u * 16 + c] = f; g_cv[u * 16 + c] = v; c++; }
    }
    g_cn[u] = c;
}

__global__ void __launch_bounds__(256) k_proj2(const float* __restrict__ x,
                                               const float* __restrict__ bias) {
    __shared__ float xs[Fv * Bv];
    int t = blockIdx.x, tid = threadIdx.x;
    for (int i = tid; i < Fv * Bv; i += 256) {
        int b = i >> 7, f = i & 127;
        xs[f * Bv + b] = x[((size_t)b * Tv + t) * Fv + f];
    }
    __syncthreads();
    int bp = tid & 7;
    for (int uc = 0; uc < 64; uc++) {
        int u = uc * 32 + (tid >> 3);
        int n = g_cn[u];
        u64 acc = dup32(bias[u]);
        for (int j = 0; j < n; j++) {
            int f = g_ci[u * 16 + j];
            float v = g_cv[u * 16 + j];
            u64 xv = *(const u64*)&xs[f * Bv + 2 * bp];
            fma2(acc, dup32(v), xv);
        }
        *(u64*)(g_u + ((size_t)t * Uv + u) * Bv + 2 * bp) = acc;
    }
}

// persistent recurrence: cta owns cols [cta*16, cta*16+16), 512 threads.
// Per-region dataflow flags instead of a global barrier; 3-slot ring, 4 tiles.
__global__ void __launch_bounds__(THR, 1) k_main(const float* __restrict__ W) {
    extern __shared__ float sm[];
    float* sW = sm;                      // [2048 k][16 col]
    float* hs = sm + Uv * CPC;           // 3 x [512 k][16 b]
    unsigned hsb = sptr(hs);
    int tid = threadIdx.x, cta = blockIdx.x, cg0 = cta * CPC;
    int lane = tid & 31;
    int cg = lane & 3, ko = lane >> 2;
    int kp = tid >> 5;
    int myreg = cta >> 5;                // this CTA's h region

    for (int idx = tid; idx < Uv * CPC / 4; idx += THR) {
        int k = idx >> 2, c4 = idx & 3;
        float4 v = *(const float4*)(W + (size_t)k * Uv + cg0 + c4 * 4);
        *(float4*)(sW + k * CPC + c4 * 4) = v;
    }
    __syncthreads();

    for (int t = 0; t < Tv; t++) {
        const float* hb = g_h[t & 1];
        unsigned tgt = 32u * (unsigned)t;
        u64 uval = 0;
        if (tid < 128)
            uval = *(const u64*)(g_u + ((size_t)t * Uv + cg0 + (tid >> 3)) * Bv + 2 * (tid & 7));

        // issue tiles 0..2 into slots 0..2, each gated by its region flag
#pragma unroll
        for (int r = 0; r < 3; r++) {
            spinflag(&g_c[r], tgt);
            unsigned d = hsb + (unsigned)(r * TK * Bv * 4);
            const float* src = hb + r * TK * Bv;
#pragma unroll
            for (int j = 0; j < 4; j++)
                cpa16(d + (unsigned)((tid + j * THR) * 16), src + (tid + j * THR) * 4);
            asm volatile("cp.async.commit_group;" ::: "memory");
        }

        u64 acc[32];
#pragma unroll
        for (int i = 0; i < 32; i++) acc[i] = 0ull;

#pragma unroll
        for (int tl = 0; tl < 4; tl++) {
            if (tl == 0)      asm volatile("cp.async.wait_group 2;" ::: "memory");
            else if (tl == 1) asm volatile("cp.async.wait_group 1;" ::: "memory");
            else if (tl == 2) asm volatile("cp.async.wait_group 1;" ::: "memory");
            else              asm volatile("cp.async.wait_group 0;" ::: "memory");
            __syncthreads();
            if (tl == 1) {
                // slot0 fully consumed (fenced by this sync) -> fetch tile3 into it
                spinflag(&g_c[3], tgt);
                unsigned d = hsb;
                const float* src = hb + 3 * TK * Bv;
#pragma unroll
                for (int j = 0; j < 4; j++)
                    cpa16(d + (unsigned)((tid + j * THR) * 16), src + (tid + j * THR) * 4);
                asm volatile("cp.async.commit_group;" ::: "memory");
            }
            const float* hbuf = hs + (tl % 3) * (TK * Bv);
#pragma unroll
            for (int i = 0; i < 4; i++) {
                int kl = kp * 32 + i * 8 + ko;
                int gk = tl * TK + kl;
                float4 wv = *((const float4*)(sW + gk * CPC) + cg);
                u64 wd[4] = { dup32(wv.x), dup32(wv.y), dup32(wv.z), dup32(wv.w) };
                const ulonglong2* hp = (const ulonglong2*)(hbuf + kl * Bv);
                ulonglong2 p0 = hp[0], p1 = hp[1], p2 = hp[2], p3 = hp[3];
                u64 h[8] = { p0.x, p0.y, p1.x, p1.y, p2.x, p2.y, p3.x, p3.y };
#pragma unroll
                for (int c = 0; c < 4; c++)
#pragma unroll
                    for (int bp = 0; bp < 8; bp++)
                        fma2(acc[c * 8 + bp], wd[c], h[bp]);
            }
        }

        // reduce-scatter over ko: lane ko ends owning flat idx [4ko..4ko+3]
#pragma unroll
        for (int m = 0; m < 16; m++) {
            u64 mine = (ko & 4) ? acc[16 + m] : acc[m];
            u64 send = (ko & 4) ? acc[m] : acc[16 + m];
            u64 r = shfl_xor64(send, 16);
            add2(mine, r); acc[m] = mine;
        }
#pragma unroll
        for (int m = 0; m < 8; m++) {
            u64 mine = (ko & 2) ? acc[8 + m] : acc[m];
            u64 send = (ko & 2) ? acc[m] : acc[8 + m];
            u64 r = shfl_xor64(send, 8);
            add2(mine, r); acc[m] = mine;
        }
#pragma unroll
        for (int m = 0; m < 4; m++) {
            u64 mine = (ko & 1) ? acc[4 + m] : acc[m];
            u64 send = (ko & 1) ? acc[m] : acc[4 + m];
            u64 r = shfl_xor64(send, 4);
            add2(mine, r); acc[m] = mine;
        }
        // stash into ring slot 1 (last read at tl=1; two syncs since) -> no guard sync
        u64* red = (u64*)(hs + TK * Bv);
        {
            int o0 = (4 * cg + (ko >> 1)) * 8 + (ko & 1) * 4;
            u64* dst = red + kp * 128 + o0;
            dst[0] = acc[0]; dst[1] = acc[1]; dst[2] = acc[2]; dst[3] = acc[3];
        }
        __syncthreads();
        if (tid < 128) {
            u64 s = uval;
#pragma unroll
            for (int k2 = 0; k2 < 16; k2++) add2(s, red[k2 * 128 + tid]);
            float lo = __uint_as_float((unsigned)(s & 0xFFFFFFFFull));
            float hi = __uint_as_float((unsigned)(s >> 32));
            float2 hn = make_float2(tanhf(lo), tanhf(hi));
            *(float2*)(g_h[(t + 1) & 1] + (cg0 + (tid >> 3)) * Bv + 2 * (tid & 7)) = hn;
        }
        __syncthreads();
        if (t < Tv - 1 && tid == 0) {
            asm volatile("red.release.gpu.global.add.u32 [%0], %1;"
                         :: "l"(&g_c[myreg]), "r"(1u) : "memory");
        }
    }
}

__global__ void k_out(const float* __restrict__ w_out,
                      const float* __restrict__ b_out, float* __restrict__ out) {
    int b = threadIdx.x >> 5, lane = threadIdx.x & 31;
    float s = 0.0f;
    for (int u = lane; u < Uv; u += 32) s += g_h[0][u * Bv + b] * w_out[u];
#pragma unroll
    for (int o = 16; o; o >>= 1) s += __shfl_xor_sync(0xFFFFFFFFu, s, o);
    if (lane == 0) out[b] = s + b_out[0];
}

extern "C" void kernel_launch(void* const* d_in, const int* in_sizes, int n_in,
                              void* d_out, int out_size) {
    const float* x     = (const float*)d_in[0];
    const float* kern  = (const float*)d_in[1];
    const float* W     = (const float*)d_in[2];
    const float* bias  = (const float*)d_in[3];
    const float* w_out = (const float*)d_in[4];
    const float* b_out = (const float*)d_in[5];
    cudaFuncSetAttribute(k_main, cudaFuncAttributeMaxDynamicSharedMemorySize, SMEM_MAIN);
    k0<<<128, 256>>>();
    k_csc<<<8, 256>>>(kern);
    k_proj2<<<Tv, 256>>>(x, bias);
    k_main<<<NCTA, THR, SMEM_MAIN>>>(W);
    k_out<<<1, 512>>>(w_out, b_out, (float*)d_out);
}

// round 15
// speedup vs baseline: 1.4609x; 1.4609x over previous
#include <cuda_runtime.h>
#include <cstdint>

#define Uv 2048
#define Bv 16
#define Tv 2048
#define Fv 128
#define NCTA 128
#define CPC 16
#define TK 512
#define THR 512
#define SMEM_MAIN (Uv*CPC*4 + 3*TK*Bv*4)   // 128KB W + 96KB h ring = 224KB

typedef unsigned long long u64;

__device__ __align__(16) float g_u[(size_t)Tv * Uv * Bv];   // [t][u][b]
__device__ __align__(16) float g_h[2][Uv * Bv];             // [buf][u][b]
__device__ __align__(128) unsigned g_c[4 * 32];             // region r counter at g_c[r*32] (padded lines)
__device__ int   g_ci[Uv * 16];
__device__ float g_cv[Uv * 16];
__device__ int   g_cn[Uv];

__device__ __forceinline__ void fma2(u64& d, u64 a, u64 b) {
    asm("fma.rn.f32x2 %0, %1, %2, %0;" : "+l"(d) : "l"(a), "l"(b));
}
__device__ __forceinline__ void add2(u64& d, u64 a) {
    asm("add.rn.f32x2 %0, %1, %0;" : "+l"(d) : "l"(a));
}
__device__ __forceinline__ u64 dup32(float x) {
    u64 d; unsigned xi = __float_as_uint(x);
    asm("mov.b64 %0, {%1, %1};" : "=l"(d) : "r"(xi)); return d;
}
__device__ __forceinline__ unsigned sptr(const void* p) {
    unsigned r;
    asm("{ .reg .u64 t; cvta.to.shared.u64 t, %1; cvt.u32.u64 %0, t; }" : "=r"(r) : "l"(p));
    return r;
}
__device__ __forceinline__ void cpa16(unsigned dst, const float* src) {
    asm volatile("cp.async.cg.shared.global [%0], [%1], 16;" :: "r"(dst), "l"(src));
}
__device__ __forceinline__ unsigned ldacq(unsigned* p) {
    unsigned v;
    asm volatile("ld.acquire.gpu.u32 %0, [%1];" : "=r"(v) : "l"(p) : "memory");
    return v;
}
__device__ __forceinline__ u64 shfl_xor64(u64 v, int d) {
    unsigned lo = (unsigned)v, hi = (unsigned)(v >> 32);
    lo = __shfl_xor_sync(0xFFFFFFFFu, lo, d);
    hi = __shfl_xor_sync(0xFFFFFFFFu, hi, d);
    return (u64)lo | ((u64)hi << 32);
}

__global__ void k0() {
    int i = blockIdx.x * blockDim.x + threadIdx.x;
    if (i < 4 * 32) g_c[i] = 0u;
    if (i < Uv * Bv) g_h[0][i] = 0.0f;
}

__global__ void k_csc(const float* __restrict__ kern) {
    int u = blockIdx.x * blockDim.x + threadIdx.x;
    if (u >= Uv) return;
    int c = 0;
    for (int f = 0; f < Fv; f++) {
        float v = kern[(size_t)f * Uv + u];
        if (v != 0.0f) { g_ci[u * 16 + c] = f; g_cv[u * 16 + c] = v; c++; }
    }
    g_cn[u] = c;
}

__global__ void __launch_bounds__(256) k_proj2(const float* __restrict__ x,
                                               const float* __restrict__ bias) {
    __shared__ float xs[Fv * Bv];
    int t = blockIdx.x, tid = threadIdx.x;
    for (int i = tid; i < Fv * Bv; i += 256) {
        int b = i >> 7, f = i & 127;
        xs[f * Bv + b] = x[((size_t)b * Tv + t) * Fv + f];
    }
    __syncthreads();
    int bp = tid & 7;
    for (int uc = 0; uc < 64; uc++) {
        int u = uc * 32 + (tid >> 3);
        int n = g_cn[u];
        u64 acc = dup32(bias[u]);
        for (int j = 0; j < n; j++) {
            int f = g_ci[u * 16 + j];
            float v = g_cv[u * 16 + j];
            u64 xv = *(const u64*)&xs[f * Bv + 2 * bp];
            fma2(acc, dup32(v), xv);
        }
        *(u64*)(g_u + ((size_t)t * Uv + u) * Bv + 2 * bp) = acc;
    }
}

// persistent recurrence: cta owns cols [cta*16, cta*16+16), 512 threads
// 4 k-tiles of 512, 3-deep smem ring, ONE syncthreads per tile.  (R12 core)
__global__ void __launch_bounds__(THR, 1) k_main(const float* __restrict__ W) {
    extern __shared__ float sm[];
    float* sW = sm;                      // [2048 k][16 col]
    float* hs = sm + Uv * CPC;           // 3 x [512 k][16 b] (32KB each)
    unsigned hsb = sptr(hs);
    int tid = threadIdx.x, cta = blockIdx.x, cg0 = cta * CPC;
    int lane = tid & 31;
    int cg = lane & 3, ko = lane >> 2;   // cg:0..3 (col quad), ko:0..7 (k offset)
    int kp = tid >> 5;                   // warp id 0..15
    int myreg = cta >> 5;                // producer region of this CTA

    for (int idx = tid; idx < Uv * CPC / 4; idx += THR) {
        int k = idx >> 2, c4 = idx & 3;
        float4 v = *(const float4*)(W + (size_t)k * Uv + cg0 + c4 * 4);
        *(float4*)(sW + k * CPC + c4 * 4) = v;
    }
    __syncthreads();

    for (int t = 0; t < Tv; t++) {
        const float* hb = g_h[t & 1];
        u64 uval = 0;
        if (tid < 128)
            uval = *(const u64*)(g_u + ((size_t)t * Uv + cg0 + (tid >> 3)) * Bv + 2 * (tid & 7));
        // prefetch tile 0 into ring slot 0 (32KB = 4 cp.async per thread)
#pragma unroll
        for (int j = 0; j < 4; j++)
            cpa16(hsb + (unsigned)((tid + j * THR) * 16), hb + (tid + j * THR) * 4);
        asm volatile("cp.async.commit_group;" ::: "memory");

        u64 acc[32];
#pragma unroll
        for (int i = 0; i < 32; i++) acc[i] = 0ull;

        for (int tl = 0; tl < 4; tl++) {
            if (tl < 3) {
                int slot = (tl + 1) % 3;
                unsigned d = hsb + (unsigned)(slot * TK * Bv * 4);
                const float* src = hb + (tl + 1) * TK * Bv;
#pragma unroll
                for (int j = 0; j < 4; j++)
                    cpa16(d + (unsigned)((tid + j * THR) * 16), src + (tid + j * THR) * 4);
                asm volatile("cp.async.commit_group;" ::: "memory");
                asm volatile("cp.async.wait_group 1;" ::: "memory");
            } else {
                asm volatile("cp.async.wait_group 0;" ::: "memory");
            }
            __syncthreads();
            const float* hbuf = hs + (tl % 3) * (TK * Bv);
#pragma unroll
            for (int i = 0; i < 4; i++) {
                int kl = kp * 32 + i * 8 + ko;          // 0..511
                int gk = tl * TK + kl;
                float4 wv = *((const float4*)(sW + gk * CPC) + cg);
                u64 wd[4] = { dup32(wv.x), dup32(wv.y), dup32(wv.z), dup32(wv.w) };
                const ulonglong2* hp = (const ulonglong2*)(hbuf + kl * Bv);
                ulonglong2 p0 = hp[0], p1 = hp[1], p2 = hp[2], p3 = hp[3];
                u64 h[8] = { p0.x, p0.y, p1.x, p1.y, p2.x, p2.y, p3.x, p3.y };
#pragma unroll
                for (int c = 0; c < 4; c++)
#pragma unroll
                    for (int bp = 0; bp < 8; bp++)
                        fma2(acc[c * 8 + bp], wd[c], h[bp]);
            }
        }

        // reduce-scatter over ko: lane ko ends owning acc[0..3] = flat idx [4ko..4ko+3]
#pragma unroll
        for (int m = 0; m < 16; m++) {
            u64 mine = (ko & 4) ? acc[16 + m] : acc[m];
            u64 send = (ko & 4) ? acc[m] : acc[16 + m];
            u64 r = shfl_xor64(send, 16);
            add2(mine, r); acc[m] = mine;
        }
#pragma unroll
        for (int m = 0; m < 8; m++) {
            u64 mine = (ko & 2) ? acc[8 + m] : acc[m];
            u64 send = (ko & 2) ? acc[m] : acc[8 + m];
            u64 r = shfl_xor64(send, 8);
            add2(mine, r); acc[m] = mine;
        }
#pragma unroll
        for (int m = 0; m < 4; m++) {
            u64 mine = (ko & 1) ? acc[4 + m] : acc[m];
            u64 send = (ko & 1) ? acc[m] : acc[4 + m];
            u64 r = shfl_xor64(send, 4);
            add2(mine, r); acc[m] = mine;
        }
        __syncthreads();   // guard: ring slot 0 (stash target) holds tile-3 data being read
        // stash partials: red[kp][o], o = col*8+bp, col = 4cg+(ko>>1), bp base = (ko&1)*4
        {
            u64* red = (u64*)hs;
            int o0 = (4 * cg + (ko >> 1)) * 8 + (ko & 1) * 4;
            u64* dst = red + kp * 128 + o0;
            dst[0] = acc[0]; dst[1] = acc[1]; dst[2] = acc[2]; dst[3] = acc[3];
        }
        __syncthreads();
        if (tid < 128) {
            u64* red = (u64*)hs;
            u64 s = uval;
#pragma unroll
            for (int k2 = 0; k2 < 16; k2++) add2(s, red[k2 * 128 + tid]);
            float lo = __uint_as_float((unsigned)(s & 0xFFFFFFFFull));
            float hi = __uint_as_float((unsigned)(s >> 32));
            float2 hn = make_float2(tanhf(lo), tanhf(hi));
            *(float2*)(g_h[(t + 1) & 1] + (cg0 + (tid >> 3)) * Bv + 2 * (tid & 7)) = hn;
        }
        __syncthreads();
        if (t < Tv - 1) {
            // split barrier: 4 padded per-region counters; tid0 increments own
            // region; tids 0-3 spin in parallel (one counter each); bar broadcasts.
            if (tid == 0) {
                asm volatile("red.release.gpu.global.add.u32 [%0], %1;"
                             :: "l"(&g_c[myreg * 32]), "r"(1u) : "memory");
            }
            if (tid < 4) {
                unsigned tgt = 32u * (unsigned)(t + 1);
                while (ldacq(&g_c[tid * 32]) < tgt) {}
            }
            __syncthreads();
        }
    }
}

__global__ void k_out(const float* __restrict__ w_out,
                      const float* __restrict__ b_out, float* __restrict__ out) {
    int b = threadIdx.x >> 5, lane = threadIdx.x & 31;
    float s = 0.0f;
    for (int u = lane; u < Uv; u += 32) s += g_h[0][u * Bv + b] * w_out[u];
#pragma unroll
    for (int o = 16; o; o >>= 1) s += __shfl_xor_sync(0xFFFFFFFFu, s, o);
    if (lane == 0) out[b] = s + b_out[0];
}

extern "C" void kernel_launch(void* const* d_in, const int* in_sizes, int n_in,
                              void* d_out, int out_size) {
    const float* x     = (const float*)d_in[0];
    const float* kern  = (const float*)d_in[1];
    const float* W     = (const float*)d_in[2];
    const float* bias  = (const float*)d_in[3];
    const float* w_out = (const float*)d_in[4];
    const float* b_out = (const float*)d_in[5];
    cudaFuncSetAttribute(k_main, cudaFuncAttributeMaxDynamicSharedMemorySize, SMEM_MAIN);
    k0<<<128, 256>>>();
    k_csc<<<8, 256>>>(kern);
    k_proj2<<<Tv, 256>>>(x, bias);
    k_main<<<NCTA, THR, SMEM_MAIN>>>(W);
    k_out<<<1, 512>>>(w_out, b_out, (float*)d_out);
}